// round 11
// baseline (speedup 1.0000x reference)
#include <cuda_runtime.h>
#include <cuda_bf16.h>
#include <math.h>
#include <stdint.h>

// Problem constants (fixed by setup_inputs): B=2048, K=128, D=256
#define BB 2048
#define KK 128
#define DD 256

#define BM 32       // b-rows per block (main kernel)
#define BN 32       // k-cols per block
#define PB 264      // smem row pitch in bf16 units (528 B; 16B-aligned, conflict-free ldmatrix)
#define NTHREADS 256

// Global scratch (allocation-free rule: __device__ arrays)
__device__ __nv_bfloat16 g_yhi[BB * DD];
__device__ __nv_bfloat16 g_ylo[BB * DD];
__device__ __nv_bfloat16 g_zhi[KK * DD];
__device__ __nv_bfloat16 g_zlo[KK * DD];
__device__ float g_y2[BB];
__device__ float g_s[KK], g_t[KK], g_x2[KK], g_xa[KK], g_an2[KK];

__device__ __forceinline__ uint32_t cvta_smem(const void* p) {
    return (uint32_t)__cvta_generic_to_shared(p);
}
__device__ __forceinline__ void cp16(uint32_t dst, const void* src) {
    asm volatile("cp.async.cg.shared.global [%0], [%1], 16;" :: "r"(dst), "l"(src));
}
__device__ __forceinline__ void cp_commit_wait_all() {
    asm volatile("cp.async.commit_group;");
    asm volatile("cp.async.wait_group 0;");
}
__device__ __forceinline__ void ldmat_x4(uint32_t* r, uint32_t addr) {
    asm volatile("ldmatrix.sync.aligned.m8n8.x4.shared.b16 {%0,%1,%2,%3}, [%4];"
                 : "=r"(r[0]), "=r"(r[1]), "=r"(r[2]), "=r"(r[3]) : "r"(addr));
}
__device__ __forceinline__ void mma_bf16(float* d, const uint32_t* a, uint32_t b0, uint32_t b1) {
    asm volatile("mma.sync.aligned.m16n8k16.row.col.f32.bf16.bf16.f32 "
                 "{%0,%1,%2,%3}, {%4,%5,%6,%7}, {%8,%9}, {%0,%1,%2,%3};"
                 : "+f"(d[0]), "+f"(d[1]), "+f"(d[2]), "+f"(d[3])
                 : "r"(a[0]), "r"(a[1]), "r"(a[2]), "r"(a[3]), "r"(b0), "r"(b1));
}
__device__ __forceinline__ uint32_t bits2(__nv_bfloat162 v) {
    return *reinterpret_cast<uint32_t*>(&v);
}

// ============ Kernel 1: split + per-row scalars (one warp per 2 rows) ============
__global__ void __launch_bounds__(256, 4)
prep_kernel(const float* __restrict__ Y, const float* __restrict__ Z,
            const float* __restrict__ R)
{
    const int warp = threadIdx.x >> 5;
    const int lane = threadIdx.x & 31;
    const bool isZ = blockIdx.x >= (BB / 16);
    const int rbase = isZ ? (blockIdx.x - BB / 16) * 16 + warp * 2
                          : blockIdx.x * 16 + warp * 2;

    #pragma unroll
    for (int rr = 0; rr < 2; rr++) {
        const int row = rbase + rr;
        if (isZ && row >= KK) break;

        const float* src = (isZ ? Z : Y) + (size_t)row * DD;
        __nv_bfloat16* hiDst = (isZ ? g_zhi : g_yhi) + (size_t)row * DD;
        __nv_bfloat16* loDst = (isZ ? g_zlo : g_ylo) + (size_t)row * DD;

        float acc = 0.f;
        #pragma unroll
        for (int j = 0; j < 2; j++) {
            int c4 = lane + 32 * j;
            float4 v = reinterpret_cast<const float4*>(src)[c4];
            __nv_bfloat162 h01 = __float22bfloat162_rn(make_float2(v.x, v.y));
            __nv_bfloat162 h23 = __float22bfloat162_rn(make_float2(v.z, v.w));
            float2 hf01 = __bfloat1622float2(h01);
            float2 hf23 = __bfloat1622float2(h23);
            __nv_bfloat162 l01 = __float22bfloat162_rn(make_float2(v.x - hf01.x, v.y - hf01.y));
            __nv_bfloat162 l23 = __float22bfloat162_rn(make_float2(v.z - hf23.x, v.w - hf23.y));
            reinterpret_cast<uint2*>(hiDst)[c4] = make_uint2(bits2(h01), bits2(h23));
            reinterpret_cast<uint2*>(loDst)[c4] = make_uint2(bits2(l01), bits2(l23));
            float2 lf01 = __bfloat1622float2(l01);
            float2 lf23 = __bfloat1622float2(l23);
            float v0 = hf01.x + lf01.x, v1 = hf01.y + lf01.y;
            float v2 = hf23.x + lf23.x, v3 = hf23.y + lf23.y;
            acc = fmaf(v0, v0, acc); acc = fmaf(v1, v1, acc);
            acc = fmaf(v2, v2, acc); acc = fmaf(v3, v3, acc);
        }
        #pragma unroll
        for (int off = 16; off > 0; off >>= 1)
            acc += __shfl_xor_sync(0xffffffffu, acc, off);

        if (lane == 0) {
            if (!isZ) {
                g_y2[row] = acc;
            } else {
                float zn2 = acc;
                float zn  = sqrtf(zn2);
                float r   = R[row];
                float un  = fmaxf(fabsf(r) * zn, 1e-15f);
                float s   = -tanhf(un) * r / un;
                float th  = tanhf(r);
                float ic2 = 1.0f - th * th;      // 1/cosh(r)^2
                float an  = zn * ic2;
                float t   = ic2 / fmaxf(an, 1e-12f);
                g_s[row]   = s;
                g_t[row]   = t;
                g_x2[row]  = s * s * zn2;
                g_xa[row]  = s * zn2 * t;
                g_an2[row] = 2.0f * an;
            }
        }
    }
}

// ============ Kernel 2: bf16 3-term MMA GEMM + hyperbolic epilogue ============
// logits[b][k] = 2*an_k * asinh( 2*(S*xa + T*ya)*den / (den^2 - (S^2*x2 + 2*S*T*xy + T^2*y2)) )
// g = z_k . y_b, xy = s_k*g, ya = t_k*g, S = 1+2xy+y2, den = 1+2xy+x2*y2, T = 1-x2

__global__ void __launch_bounds__(NTHREADS, 3)
mlr_logits_kernel(float* __restrict__ Out)       // (B, K)
{
    extern __shared__ char smem[];
    __nv_bfloat16* AHI = reinterpret_cast<__nv_bfloat16*>(smem);           // BM*PB
    __nv_bfloat16* ALO = AHI + BM * PB;                                     // BM*PB
    __nv_bfloat16* ZHI = ALO + BM * PB;                                     // BN*PB
    __nv_bfloat16* ZLO = ZHI + BN * PB;                                     // BN*PB
    float* s_s   = reinterpret_cast<float*>(ZLO + BN * PB);                 // BN
    float* s_t   = s_s + BN;
    float* s_x2  = s_t + BN;
    float* s_xa  = s_x2 + BN;
    float* s_an2 = s_xa + BN;
    float* s_y2  = s_an2 + BN;                                              // BM

    const int tid  = threadIdx.x;
    const int b0   = blockIdx.x * BM;
    const int k0   = blockIdx.y * BN;
    const int warp = tid >> 5;
    const int lane = tid & 31;

    const uint32_t sAHI = cvta_smem(AHI);
    const uint32_t sALO = cvta_smem(ALO);
    const uint32_t sZHI = cvta_smem(ZHI);
    const uint32_t sZLO = cvta_smem(ZLO);

    // ---- cp.async tile copies: 16 per thread, no register round-trip ----
    #pragma unroll
    for (int idx = tid; idx < BM * 32; idx += NTHREADS) {
        int row = idx >> 5;
        int c8  = idx & 31;
        size_t goff = (size_t)(b0 + row) * DD + c8 * 8;
        uint32_t soff = (row * PB + c8 * 8) * 2;
        cp16(sAHI + soff, &g_yhi[goff]);
        cp16(sALO + soff, &g_ylo[goff]);
    }
    #pragma unroll
    for (int idx = tid; idx < BN * 32; idx += NTHREADS) {
        int row = idx >> 5;
        int c8  = idx & 31;
        size_t goff = (size_t)(k0 + row) * DD + c8 * 8;
        uint32_t soff = (row * PB + c8 * 8) * 2;
        cp16(sZHI + soff, &g_zhi[goff]);
        cp16(sZLO + soff, &g_zlo[goff]);
    }
    // ---- stage scalars while copies fly ----
    if (tid < BM) {
        s_y2[tid] = g_y2[b0 + tid];
    } else if (tid < BM + BN) {
        int row = tid - BM;
        s_s[row]   = g_s[k0 + row];
        s_t[row]   = g_t[k0 + row];
        s_x2[row]  = g_x2[k0 + row];
        s_xa[row]  = g_xa[k0 + row];
        s_an2[row] = g_an2[k0 + row];
    }
    cp_commit_wait_all();
    __syncthreads();

    // ---- tensor GEMM: 8 warps (2m x 4n), warp tile 16m x 8n, m16n8k16 bf16 ----
    const int mw = (warp >> 2) * 16;      // 0,16
    const int nw = (warp & 3) * 8;        // 0,8,16,24
    const int g  = lane >> 2;
    const int c  = lane & 3;

    const int rowA = mw + (lane & 15);
    const int offA = (lane >> 4) * 16;             // bytes
    const int rowB = nw + (lane & 7);
    const int offB = (lane >> 3) * 16;             // bytes: 0,16,32,48

    uint32_t aAH = sAHI + rowA * (PB * 2) + offA;
    uint32_t aAL = sALO + rowA * (PB * 2) + offA;
    uint32_t aBH = sZHI + rowB * (PB * 2) + offB;
    uint32_t aBL = sZLO + rowB * (PB * 2) + offB;

    float accP[4] = {0,0,0,0};   // hi*hi
    float accQ[4] = {0,0,0,0};   // hi*lo
    float accS[4] = {0,0,0,0};   // lo*hi

    #pragma unroll
    for (int t = 0; t < DD / 32; t++) {          // 8 iterations of k32
        const uint32_t oA = t * 64;              // 32 bf16 = 64 bytes
        uint32_t aH0[4], aH1[4], aL0[4], aL1[4], bH[4], bL[4];
        ldmat_x4(aH0, aAH + oA);
        ldmat_x4(aH1, aAH + oA + 32);
        ldmat_x4(aL0, aAL + oA);
        ldmat_x4(aL1, aAL + oA + 32);
        ldmat_x4(bH,  aBH + oA);
        ldmat_x4(bL,  aBL + oA);

        mma_bf16(accP, aH0, bH[0], bH[1]);
        mma_bf16(accQ, aH0, bL[0], bL[1]);
        mma_bf16(accS, aL0, bH[0], bH[1]);
        mma_bf16(accP, aH1, bH[2], bH[3]);
        mma_bf16(accQ, aH1, bL[2], bL[3]);
        mma_bf16(accS, aL1, bH[2], bH[3]);
    }

    // ---- epilogue: 4 outputs per thread, float2 stores ----
    const int brow[2] = { mw + g, mw + g + 8 };
    const int kl = nw + 2 * c;
    const float s0  = s_s[kl],   s1  = s_s[kl + 1];
    const float t0  = s_t[kl],   t1  = s_t[kl + 1];
    const float x20 = s_x2[kl],  x21 = s_x2[kl + 1];
    const float xa0 = s_xa[kl],  xa1 = s_xa[kl + 1];
    const float a20 = s_an2[kl], a21 = s_an2[kl + 1];
    const float T0 = 1.0f - x20, T1 = 1.0f - x21;

    #pragma unroll
    for (int i = 0; i < 2; i++) {
        const float y2 = s_y2[brow[i]];
        const float g0 = accP[i * 2 + 0] + accQ[i * 2 + 0] + accS[i * 2 + 0];
        const float g1 = accP[i * 2 + 1] + accQ[i * 2 + 1] + accS[i * 2 + 1];

        float xy = s0 * g0;
        float ya = t0 * g0;
        float Sv  = fmaf(2.0f, xy, 1.0f) + y2;
        float den = fmaf(2.0f, xy, 1.0f) + x20 * y2;
        float Pv  = Sv * Sv * x20 + 2.0f * Sv * T0 * xy + T0 * T0 * y2;
        float v0  = 2.0f * (Sv * xa0 + T0 * ya) * den / (den * den - Pv);
        float o0  = a20 * asinhf(v0);

        xy  = s1 * g1;
        ya  = t1 * g1;
        Sv  = fmaf(2.0f, xy, 1.0f) + y2;
        den = fmaf(2.0f, xy, 1.0f) + x21 * y2;
        Pv  = Sv * Sv * x21 + 2.0f * Sv * T1 * xy + T1 * T1 * y2;
        float v1 = 2.0f * (Sv * xa1 + T1 * ya) * den / (den * den - Pv);
        float o1 = a21 * asinhf(v1);

        *reinterpret_cast<float2*>(&Out[(size_t)(b0 + brow[i]) * KK + (k0 + kl)]) =
            make_float2(o0, o1);
    }
}

extern "C" void kernel_launch(void* const* d_in, const int* in_sizes, int n_in,
                              void* d_out, int out_size)
{
    const float* Y = (const float*)d_in[0];   // output_before (2048, 256)
    const float* Z = (const float*)d_in[1];   // z_mlr (128, 256)
    const float* R = (const float*)d_in[2];   // mlr_r (128, 1)
    float* Out = (float*)d_out;               // (2048, 128)

    // Kernel 1: split + scalars.  128 Y-blocks + 8 Z-blocks (16 rows each).
    prep_kernel<<<BB / 16 + KK / 16, 256>>>(Y, Z, R);

    // Kernel 2: GEMM + epilogue.
    size_t shmem = (size_t)(2 * BM * PB + 2 * BN * PB) * sizeof(__nv_bfloat16)
                 + (size_t)(5 * BN + BM) * sizeof(float);
    cudaFuncSetAttribute(mlr_logits_kernel,
                         cudaFuncAttributeMaxDynamicSharedMemorySize, (int)shmem);
    dim3 grid(BB / BM, KK / BN);   // 64 x 4 = 256 blocks
    mlr_logits_kernel<<<grid, NTHREADS, shmem>>>(Out);
}

// round 12
// speedup vs baseline: 1.2186x; 1.2186x over previous
#include <cuda_runtime.h>
#include <cuda_bf16.h>
#include <math.h>
#include <stdint.h>

// Problem constants (fixed by setup_inputs): B=2048, K=128, D=256
#define BB 2048
#define KK 128
#define DD 256

#define BM 32       // b-rows per block
#define BN 32       // k-cols per block
#define PB 264      // smem row pitch in bf16 units (528 B; 16B-aligned, conflict-free ldmatrix)
#define NTHREADS 256

__device__ __forceinline__ uint32_t cvta_smem(const void* p) {
    return (uint32_t)__cvta_generic_to_shared(p);
}
__device__ __forceinline__ void ldmat_x4(uint32_t* r, uint32_t addr) {
    asm volatile("ldmatrix.sync.aligned.m8n8.x4.shared.b16 {%0,%1,%2,%3}, [%4];"
                 : "=r"(r[0]), "=r"(r[1]), "=r"(r[2]), "=r"(r[3]) : "r"(addr));
}
__device__ __forceinline__ void mma_bf16(float* d, const uint32_t* a, uint32_t b0, uint32_t b1) {
    asm volatile("mma.sync.aligned.m16n8k16.row.col.f32.bf16.bf16.f32 "
                 "{%0,%1,%2,%3}, {%4,%5,%6,%7}, {%8,%9}, {%0,%1,%2,%3};"
                 : "+f"(d[0]), "+f"(d[1]), "+f"(d[2]), "+f"(d[3])
                 : "r"(a[0]), "r"(a[1]), "r"(a[2]), "r"(a[3]), "r"(b0), "r"(b1));
}
__device__ __forceinline__ uint32_t bits2(__nv_bfloat162 v) {
    return *reinterpret_cast<uint32_t*>(&v);
}

// Split one row (256 fp32) into truncated-bf16 hi + RN-bf16 lo, warp-collective,
// coalesced; returns this lane's partial sum of v^2 (fp32).
__device__ __forceinline__ float split_row(const float* __restrict__ src,
                                           __nv_bfloat16* hiRow,
                                           __nv_bfloat16* loRow,
                                           int lane)
{
    float acc = 0.f;
    const float4* s4 = reinterpret_cast<const float4*>(src);
    #pragma unroll
    for (int j = 0; j < 2; j++) {
        int c4 = lane + 32 * j;
        float4 v = s4[c4];
        acc = fmaf(v.x, v.x, acc);
        acc = fmaf(v.y, v.y, acc);
        acc = fmaf(v.z, v.z, acc);
        acc = fmaf(v.w, v.w, acc);
        uint32_t bx = __float_as_uint(v.x), by = __float_as_uint(v.y);
        uint32_t bz = __float_as_uint(v.z), bw = __float_as_uint(v.w);
        uint32_t hi01 = __byte_perm(bx, by, 0x7632);   // lo16=hi(x), hi16=hi(y)
        uint32_t hi23 = __byte_perm(bz, bw, 0x7632);
        float rx = v.x - __uint_as_float(bx & 0xFFFF0000u);
        float ry = v.y - __uint_as_float(by & 0xFFFF0000u);
        float rz = v.z - __uint_as_float(bz & 0xFFFF0000u);
        float rw = v.w - __uint_as_float(bw & 0xFFFF0000u);
        __nv_bfloat162 lo01 = __float22bfloat162_rn(make_float2(rx, ry));
        __nv_bfloat162 lo23 = __float22bfloat162_rn(make_float2(rz, rw));
        *reinterpret_cast<uint2*>(&hiRow[c4 * 4]) = make_uint2(hi01, hi23);
        *reinterpret_cast<uint2*>(&loRow[c4 * 4]) = make_uint2(bits2(lo01), bits2(lo23));
    }
    return acc;
}

// logits[b][k] = 2*an_k * asinh( 2*(S*xa + T*ya)*den / (den^2 - (S^2*x2 + 2*S*T*xy + T^2*y2)) )
// g = z_k . y_b, xy = s_k*g, ya = t_k*g, S = 1+2xy+y2, den = 1+2xy+x2*y2, T = 1-x2

__global__ void __launch_bounds__(NTHREADS, 3)
mlr_logits_kernel(const float* __restrict__ Y,   // output_before (B, D)
                  const float* __restrict__ Z,   // z_mlr (K, D)
                  const float* __restrict__ R,   // mlr_r (K, 1)
                  float* __restrict__ Out)       // (B, K)
{
    extern __shared__ char smem[];
    __nv_bfloat16* AHI = reinterpret_cast<__nv_bfloat16*>(smem);           // BM*PB
    __nv_bfloat16* ALO = AHI + BM * PB;                                     // BM*PB
    __nv_bfloat16* ZHI = ALO + BM * PB;                                     // BN*PB
    __nv_bfloat16* ZLO = ZHI + BN * PB;                                     // BN*PB
    float* s_s   = reinterpret_cast<float*>(ZLO + BN * PB);                 // BN
    float* s_t   = s_s + BN;
    float* s_x2  = s_t + BN;
    float* s_xa  = s_x2 + BN;
    float* s_an2 = s_xa + BN;
    float* s_y2  = s_an2 + BN;                                              // BM
    float* s_zn2 = s_y2 + BM;                                               // BN

    const int tid  = threadIdx.x;
    const int b0   = blockIdx.x * BM;
    const int k0   = blockIdx.y * BN;
    const int warp = tid >> 5;
    const int lane = tid & 31;

    // ---- in-block split: warp w handles Y rows 4w..4w+3 and Z rows 4w..4w+3 ----
    #pragma unroll
    for (int rr = 0; rr < 4; rr++) {
        const int row = warp * 4 + rr;
        float accY = split_row(Y + (size_t)(b0 + row) * DD,
                               &AHI[row * PB], &ALO[row * PB], lane);
        float accZ = split_row(Z + (size_t)(k0 + row) * DD,
                               &ZHI[row * PB], &ZLO[row * PB], lane);
        #pragma unroll
        for (int off = 16; off > 0; off >>= 1) {
            accY += __shfl_xor_sync(0xffffffffu, accY, off);
            accZ += __shfl_xor_sync(0xffffffffu, accZ, off);
        }
        if (lane == 0) {
            s_y2[row]  = accY;
            s_zn2[row] = accZ;
        }
    }
    __syncthreads();

    // ---- per-k scalars (threads 0..31) ----
    if (tid < BN) {
        float zn2 = s_zn2[tid];
        float zn  = sqrtf(zn2);
        float r   = R[k0 + tid];
        float un  = fmaxf(fabsf(r) * zn, 1e-15f);
        float s   = -tanhf(un) * r / un;
        float th  = tanhf(r);
        float ic2 = 1.0f - th * th;      // 1/cosh(r)^2
        float an  = zn * ic2;
        float t   = ic2 / fmaxf(an, 1e-12f);
        s_s[tid]   = s;
        s_t[tid]   = t;
        s_x2[tid]  = s * s * zn2;
        s_xa[tid]  = s * zn2 * t;
        s_an2[tid] = 2.0f * an;
    }
    __syncthreads();

    // ---- tensor GEMM: 8 warps (2m x 4n), warp tile 16m x 8n, m16n8k16 bf16 ----
    const int mw = (warp >> 2) * 16;      // 0,16
    const int nw = (warp & 3) * 8;        // 0,8,16,24
    const int g  = lane >> 2;
    const int c  = lane & 3;

    const int rowA = mw + (lane & 15);
    const int offA = (lane >> 4) * 16;             // bytes
    const int rowB = nw + (lane & 7);
    const int offB = (lane >> 3) * 16;             // bytes: 0,16,32,48

    const uint32_t sAHI = cvta_smem(AHI);
    const uint32_t sALO = cvta_smem(ALO);
    const uint32_t sZHI = cvta_smem(ZHI);
    const uint32_t sZLO = cvta_smem(ZLO);

    uint32_t aAH = sAHI + rowA * (PB * 2) + offA;
    uint32_t aAL = sALO + rowA * (PB * 2) + offA;
    uint32_t aBH = sZHI + rowB * (PB * 2) + offB;
    uint32_t aBL = sZLO + rowB * (PB * 2) + offB;

    float accP[4] = {0,0,0,0};   // hi*hi
    float accQ[4] = {0,0,0,0};   // hi*lo
    float accS[4] = {0,0,0,0};   // lo*hi

    #pragma unroll
    for (int t = 0; t < DD / 32; t++) {          // 8 iterations of k32
        const uint32_t oA = t * 64;              // 32 bf16 = 64 bytes
        uint32_t aH0[4], aH1[4], aL0[4], aL1[4], bH[4], bL[4];
        ldmat_x4(aH0, aAH + oA);
        ldmat_x4(aH1, aAH + oA + 32);
        ldmat_x4(aL0, aAL + oA);
        ldmat_x4(aL1, aAL + oA + 32);
        ldmat_x4(bH,  aBH + oA);
        ldmat_x4(bL,  aBL + oA);

        mma_bf16(accP, aH0, bH[0], bH[1]);
        mma_bf16(accQ, aH0, bL[0], bL[1]);
        mma_bf16(accS, aL0, bH[0], bH[1]);
        mma_bf16(accP, aH1, bH[2], bH[3]);
        mma_bf16(accQ, aH1, bL[2], bL[3]);
        mma_bf16(accS, aL1, bH[2], bH[3]);
    }

    // ---- epilogue: 4 outputs per thread, float2 stores ----
    const int brow[2] = { mw + g, mw + g + 8 };
    const int kl = nw + 2 * c;
    const float s0  = s_s[kl],   s1  = s_s[kl + 1];
    const float t0  = s_t[kl],   t1  = s_t[kl + 1];
    const float x20 = s_x2[kl],  x21 = s_x2[kl + 1];
    const float xa0 = s_xa[kl],  xa1 = s_xa[kl + 1];
    const float a20 = s_an2[kl], a21 = s_an2[kl + 1];
    const float T0 = 1.0f - x20, T1 = 1.0f - x21;

    #pragma unroll
    for (int i = 0; i < 2; i++) {
        const float y2 = s_y2[brow[i]];
        const float g0 = accP[i * 2 + 0] + accQ[i * 2 + 0] + accS[i * 2 + 0];
        const float g1 = accP[i * 2 + 1] + accQ[i * 2 + 1] + accS[i * 2 + 1];

        float xy = s0 * g0;
        float ya = t0 * g0;
        float Sv  = fmaf(2.0f, xy, 1.0f) + y2;
        float den = fmaf(2.0f, xy, 1.0f) + x20 * y2;
        float Pv  = Sv * Sv * x20 + 2.0f * Sv * T0 * xy + T0 * T0 * y2;
        float v0  = 2.0f * (Sv * xa0 + T0 * ya) * den / (den * den - Pv);
        float o0  = a20 * asinhf(v0);

        xy  = s1 * g1;
        ya  = t1 * g1;
        Sv  = fmaf(2.0f, xy, 1.0f) + y2;
        den = fmaf(2.0f, xy, 1.0f) + x21 * y2;
        Pv  = Sv * Sv * x21 + 2.0f * Sv * T1 * xy + T1 * T1 * y2;
        float v1 = 2.0f * (Sv * xa1 + T1 * ya) * den / (den * den - Pv);
        float o1 = a21 * asinhf(v1);

        *reinterpret_cast<float2*>(&Out[(size_t)(b0 + brow[i]) * KK + (k0 + kl)]) =
            make_float2(o0, o1);
    }
}

extern "C" void kernel_launch(void* const* d_in, const int* in_sizes, int n_in,
                              void* d_out, int out_size)
{
    const float* Y = (const float*)d_in[0];   // output_before (2048, 256)
    const float* Z = (const float*)d_in[1];   // z_mlr (128, 256)
    const float* R = (const float*)d_in[2];   // mlr_r (128, 1)
    float* Out = (float*)d_out;               // (2048, 128)

    size_t shmem = (size_t)(2 * BM * PB + 2 * BN * PB) * sizeof(__nv_bfloat16)
                 + (size_t)(5 * BN + BM + BN) * sizeof(float);
    cudaFuncSetAttribute(mlr_logits_kernel,
                         cudaFuncAttributeMaxDynamicSharedMemorySize, (int)shmem);

    dim3 grid(BB / BM, KK / BN);   // 64 x 4 = 256 blocks
    mlr_logits_kernel<<<grid, NTHREADS, shmem>>>(Y, Z, R, Out);
}

// round 13
// speedup vs baseline: 1.4132x; 1.1597x over previous
#include <cuda_runtime.h>
#include <cuda_bf16.h>
#include <math.h>
#include <stdint.h>

// Problem constants (fixed by setup_inputs): B=2048, K=128, D=256
#define BB 2048
#define KK 128
#define DD 256

#define BM 32       // b-rows per block
#define BN 32       // k-cols per block
#define PB 264      // smem row pitch in bf16 units (528 B; 16B-aligned, conflict-free ldmatrix)
#define NTHREADS 256

__device__ __forceinline__ uint32_t cvta_smem(const void* p) {
    return (uint32_t)__cvta_generic_to_shared(p);
}
__device__ __forceinline__ void ldmat_x4(uint32_t* r, uint32_t addr) {
    asm volatile("ldmatrix.sync.aligned.m8n8.x4.shared.b16 {%0,%1,%2,%3}, [%4];"
                 : "=r"(r[0]), "=r"(r[1]), "=r"(r[2]), "=r"(r[3]) : "r"(addr));
}
__device__ __forceinline__ void mma_bf16(float* d, const uint32_t* a, uint32_t b0, uint32_t b1) {
    asm volatile("mma.sync.aligned.m16n8k16.row.col.f32.bf16.bf16.f32 "
                 "{%0,%1,%2,%3}, {%4,%5,%6,%7}, {%8,%9}, {%0,%1,%2,%3};"
                 : "+f"(d[0]), "+f"(d[1]), "+f"(d[2]), "+f"(d[3])
                 : "r"(a[0]), "r"(a[1]), "r"(a[2]), "r"(a[3]), "r"(b0), "r"(b1));
}
__device__ __forceinline__ uint32_t bits2(__nv_bfloat162 v) {
    return *reinterpret_cast<uint32_t*>(&v);
}

// fast asinh: sign(v) * log(|v| + sqrt(v^2+1)), MUFU-based
__device__ __forceinline__ float fast_asinh(float v) {
    float av = fabsf(v);
    float w  = __logf(av + __fsqrt_rn(fmaf(av, av, 1.0f)));
    return copysignf(w, v);
}
// fast tanh for x >= 0 (also fine for any x): 1 - 2/(e^{2x}+1)
__device__ __forceinline__ float fast_tanh(float x) {
    float e2 = __expf(2.0f * x);
    return 1.0f - __fdividef(2.0f, e2 + 1.0f);
}

// Split a loaded float4 into truncated-bf16 hi + RN-bf16 lo, store to smem; add v^2 to acc.
__device__ __forceinline__ void split_store(float4 v, __nv_bfloat16* hiRow,
                                            __nv_bfloat16* loRow, int c4, float& acc)
{
    acc = fmaf(v.x, v.x, acc);
    acc = fmaf(v.y, v.y, acc);
    acc = fmaf(v.z, v.z, acc);
    acc = fmaf(v.w, v.w, acc);
    uint32_t bx = __float_as_uint(v.x), by = __float_as_uint(v.y);
    uint32_t bz = __float_as_uint(v.z), bw = __float_as_uint(v.w);
    uint32_t hi01 = __byte_perm(bx, by, 0x7632);
    uint32_t hi23 = __byte_perm(bz, bw, 0x7632);
    float rx = v.x - __uint_as_float(bx & 0xFFFF0000u);
    float ry = v.y - __uint_as_float(by & 0xFFFF0000u);
    float rz = v.z - __uint_as_float(bz & 0xFFFF0000u);
    float rw = v.w - __uint_as_float(bw & 0xFFFF0000u);
    __nv_bfloat162 lo01 = __float22bfloat162_rn(make_float2(rx, ry));
    __nv_bfloat162 lo23 = __float22bfloat162_rn(make_float2(rz, rw));
    *reinterpret_cast<uint2*>(&hiRow[c4 * 4]) = make_uint2(hi01, hi23);
    *reinterpret_cast<uint2*>(&loRow[c4 * 4]) = make_uint2(bits2(lo01), bits2(lo23));
}

// logits[b][k] = 2*an_k * asinh( 2*(S*xa + T*ya)*den / (den^2 - (S^2*x2 + 2*S*T*xy + T^2*y2)) )
// g = z_k . y_b, xy = s_k*g, ya = t_k*g, S = 1+2xy+y2, den = 1+2xy+x2*y2, T = 1-x2

__global__ void __launch_bounds__(NTHREADS, 2)
mlr_logits_kernel(const float* __restrict__ Y,   // output_before (B, D)
                  const float* __restrict__ Z,   // z_mlr (K, D)
                  const float* __restrict__ R,   // mlr_r (K, 1)
                  float* __restrict__ Out)       // (B, K)
{
    extern __shared__ char smem[];
    __nv_bfloat16* AHI = reinterpret_cast<__nv_bfloat16*>(smem);           // BM*PB
    __nv_bfloat16* ALO = AHI + BM * PB;                                     // BM*PB
    __nv_bfloat16* ZHI = ALO + BM * PB;                                     // BN*PB
    __nv_bfloat16* ZLO = ZHI + BN * PB;                                     // BN*PB
    float* s_s   = reinterpret_cast<float*>(ZLO + BN * PB);                 // BN
    float* s_t   = s_s + BN;
    float* s_x2  = s_t + BN;
    float* s_xa  = s_x2 + BN;
    float* s_an2 = s_xa + BN;
    float* s_y2  = s_an2 + BN;                                              // BM
    float* s_zn2 = s_y2 + BM;                                               // BN

    const int tid  = threadIdx.x;
    const int b0   = blockIdx.x * BM;
    const int k0   = blockIdx.y * BN;
    const int warp = tid >> 5;
    const int lane = tid & 31;

    // ---- split phase: warp w owns Y rows 4w..4w+3 and Z rows 4w..4w+3 ----
    // Process 2 batches of (2 Y-rows + 2 Z-rows): 8 independent LDG.128 per batch.
    #pragma unroll
    for (int pp = 0; pp < 2; pp++) {
        const int r0 = warp * 4 + pp * 2;
        const float4* y0 = reinterpret_cast<const float4*>(Y + (size_t)(b0 + r0) * DD);
        const float4* y1 = reinterpret_cast<const float4*>(Y + (size_t)(b0 + r0 + 1) * DD);
        const float4* z0 = reinterpret_cast<const float4*>(Z + (size_t)(k0 + r0) * DD);
        const float4* z1 = reinterpret_cast<const float4*>(Z + (size_t)(k0 + r0 + 1) * DD);
        const int cA = lane, cB = lane + 32;
        // batched loads (8 independent)
        float4 vy0a = y0[cA], vy0b = y0[cB];
        float4 vy1a = y1[cA], vy1b = y1[cB];
        float4 vz0a = z0[cA], vz0b = z0[cB];
        float4 vz1a = z1[cA], vz1b = z1[cB];

        float aY0 = 0.f, aY1 = 0.f, aZ0 = 0.f, aZ1 = 0.f;
        split_store(vy0a, &AHI[(r0    ) * PB], &ALO[(r0    ) * PB], cA, aY0);
        split_store(vy0b, &AHI[(r0    ) * PB], &ALO[(r0    ) * PB], cB, aY0);
        split_store(vy1a, &AHI[(r0 + 1) * PB], &ALO[(r0 + 1) * PB], cA, aY1);
        split_store(vy1b, &AHI[(r0 + 1) * PB], &ALO[(r0 + 1) * PB], cB, aY1);
        split_store(vz0a, &ZHI[(r0    ) * PB], &ZLO[(r0    ) * PB], cA, aZ0);
        split_store(vz0b, &ZHI[(r0    ) * PB], &ZLO[(r0    ) * PB], cB, aZ0);
        split_store(vz1a, &ZHI[(r0 + 1) * PB], &ZLO[(r0 + 1) * PB], cA, aZ1);
        split_store(vz1b, &ZHI[(r0 + 1) * PB], &ZLO[(r0 + 1) * PB], cB, aZ1);

        // 4 concurrent butterfly reductions
        #pragma unroll
        for (int off = 16; off > 0; off >>= 1) {
            aY0 += __shfl_xor_sync(0xffffffffu, aY0, off);
            aY1 += __shfl_xor_sync(0xffffffffu, aY1, off);
            aZ0 += __shfl_xor_sync(0xffffffffu, aZ0, off);
            aZ1 += __shfl_xor_sync(0xffffffffu, aZ1, off);
        }
        if (lane == 0) {
            s_y2[r0]      = aY0;
            s_y2[r0 + 1]  = aY1;
            s_zn2[r0]     = aZ0;
            s_zn2[r0 + 1] = aZ1;
        }
    }
    __syncthreads();

    // ---- per-k scalars (threads 0..31), fast transcendentals ----
    if (tid < BN) {
        float zn2 = s_zn2[tid];
        float zn  = __fsqrt_rn(zn2);
        float r   = R[k0 + tid];
        float un  = fmaxf(fabsf(r) * zn, 1e-15f);
        float s   = -fast_tanh(un) * __fdividef(r, un);
        float th  = fast_tanh(r);
        float ic2 = 1.0f - th * th;      // 1/cosh(r)^2
        float an  = zn * ic2;
        float t   = __fdividef(ic2, fmaxf(an, 1e-12f));
        s_s[tid]   = s;
        s_t[tid]   = t;
        s_x2[tid]  = s * s * zn2;
        s_xa[tid]  = s * zn2 * t;
        s_an2[tid] = 2.0f * an;
    }
    __syncthreads();

    // ---- tensor GEMM: 8 warps (2m x 4n), warp tile 16m x 8n, m16n8k16 bf16 ----
    const int mw = (warp >> 2) * 16;      // 0,16
    const int nw = (warp & 3) * 8;        // 0,8,16,24
    const int g  = lane >> 2;
    const int c  = lane & 3;

    const int rowA = mw + (lane & 15);
    const int offA = (lane >> 4) * 16;             // bytes
    const int rowB = nw + (lane & 7);
    const int offB = (lane >> 3) * 16;             // bytes: 0,16,32,48

    uint32_t aAH = cvta_smem(AHI) + rowA * (PB * 2) + offA;
    uint32_t aAL = cvta_smem(ALO) + rowA * (PB * 2) + offA;
    uint32_t aBH = cvta_smem(ZHI) + rowB * (PB * 2) + offB;
    uint32_t aBL = cvta_smem(ZLO) + rowB * (PB * 2) + offB;

    float accP[4] = {0,0,0,0};   // hi*hi
    float accQ[4] = {0,0,0,0};   // hi*lo
    float accS[4] = {0,0,0,0};   // lo*hi

    // double-buffered fragments
    uint32_t aH0[2][4], aH1[2][4], aL0[2][4], aL1[2][4], bH[2][4], bL[2][4];

    ldmat_x4(aH0[0], aAH);
    ldmat_x4(aH1[0], aAH + 32);
    ldmat_x4(aL0[0], aAL);
    ldmat_x4(aL1[0], aAL + 32);
    ldmat_x4(bH[0],  aBH);
    ldmat_x4(bL[0],  aBL);

    #pragma unroll
    for (int t = 0; t < DD / 32; t++) {          // 8 iterations of k32
        const int cur = t & 1, nxt = cur ^ 1;
        if (t < DD / 32 - 1) {
            const uint32_t oA = (t + 1) * 64;    // 32 bf16 = 64 bytes
            ldmat_x4(aH0[nxt], aAH + oA);
            ldmat_x4(aH1[nxt], aAH + oA + 32);
            ldmat_x4(aL0[nxt], aAL + oA);
            ldmat_x4(aL1[nxt], aAL + oA + 32);
            ldmat_x4(bH[nxt],  aBH + oA);
            ldmat_x4(bL[nxt],  aBL + oA);
        }
        mma_bf16(accP, aH0[cur], bH[cur][0], bH[cur][1]);
        mma_bf16(accQ, aH0[cur], bL[cur][0], bL[cur][1]);
        mma_bf16(accS, aL0[cur], bH[cur][0], bH[cur][1]);
        mma_bf16(accP, aH1[cur], bH[cur][2], bH[cur][3]);
        mma_bf16(accQ, aH1[cur], bL[cur][2], bL[cur][3]);
        mma_bf16(accS, aL1[cur], bH[cur][2], bH[cur][3]);
    }

    // ---- epilogue: 4 outputs per thread, float2 stores, fast asinh ----
    const int brow[2] = { mw + g, mw + g + 8 };
    const int kl = nw + 2 * c;
    const float s0  = s_s[kl],   s1  = s_s[kl + 1];
    const float t0  = s_t[kl],   t1  = s_t[kl + 1];
    const float x20 = s_x2[kl],  x21 = s_x2[kl + 1];
    const float xa0 = s_xa[kl],  xa1 = s_xa[kl + 1];
    const float a20 = s_an2[kl], a21 = s_an2[kl + 1];
    const float T0 = 1.0f - x20, T1 = 1.0f - x21;

    #pragma unroll
    for (int i = 0; i < 2; i++) {
        const float y2 = s_y2[brow[i]];
        const float g0 = accP[i * 2 + 0] + accQ[i * 2 + 0] + accS[i * 2 + 0];
        const float g1 = accP[i * 2 + 1] + accQ[i * 2 + 1] + accS[i * 2 + 1];

        float xy = s0 * g0;
        float ya = t0 * g0;
        float Sv  = fmaf(2.0f, xy, 1.0f) + y2;
        float den = fmaf(2.0f, xy, 1.0f) + x20 * y2;
        float Pv  = Sv * Sv * x20 + 2.0f * Sv * T0 * xy + T0 * T0 * y2;
        float v0  = 2.0f * (Sv * xa0 + T0 * ya) * __fdividef(den, den * den - Pv);
        float o0  = a20 * fast_asinh(v0);

        xy  = s1 * g1;
        ya  = t1 * g1;
        Sv  = fmaf(2.0f, xy, 1.0f) + y2;
        den = fmaf(2.0f, xy, 1.0f) + x21 * y2;
        Pv  = Sv * Sv * x21 + 2.0f * Sv * T1 * xy + T1 * T1 * y2;
        float v1 = 2.0f * (Sv * xa1 + T1 * ya) * __fdividef(den, den * den - Pv);
        float o1 = a21 * fast_asinh(v1);

        *reinterpret_cast<float2*>(&Out[(size_t)(b0 + brow[i]) * KK + (k0 + kl)]) =
            make_float2(o0, o1);
    }
}

extern "C" void kernel_launch(void* const* d_in, const int* in_sizes, int n_in,
                              void* d_out, int out_size)
{
    const float* Y = (const float*)d_in[0];   // output_before (2048, 256)
    const float* Z = (const float*)d_in[1];   // z_mlr (128, 256)
    const float* R = (const float*)d_in[2];   // mlr_r (128, 1)
    float* Out = (float*)d_out;               // (2048, 128)

    size_t shmem = (size_t)(2 * BM * PB + 2 * BN * PB) * sizeof(__nv_bfloat16)
                 + (size_t)(5 * BN + BM + BN) * sizeof(float);
    cudaFuncSetAttribute(mlr_logits_kernel,
                         cudaFuncAttributeMaxDynamicSharedMemorySize, (int)shmem);

    dim3 grid(BB / BM, KK / BN);   // 64 x 4 = 256 blocks
    mlr_logits_kernel<<<grid, NTHREADS, shmem>>>(Y, Z, R, Out);
}

// round 14
// speedup vs baseline: 1.4433x; 1.0213x over previous
#include <cuda_runtime.h>
#include <cuda_bf16.h>
#include <math.h>
#include <stdint.h>

// Problem constants (fixed by setup_inputs): B=2048, K=128, D=256
#define BB 2048
#define KK 128
#define DD 256

#define BM 32       // b-rows per block
#define BN 32       // k-cols per block
#define PB 264      // smem row pitch in bf16 units (528 B; 16B-aligned, conflict-free ldmatrix)
#define NTHREADS 256

__device__ __forceinline__ uint32_t cvta_smem(const void* p) {
    return (uint32_t)__cvta_generic_to_shared(p);
}
__device__ __forceinline__ void ldmat_x4(uint32_t* r, uint32_t addr) {
    asm volatile("ldmatrix.sync.aligned.m8n8.x4.shared.b16 {%0,%1,%2,%3}, [%4];"
                 : "=r"(r[0]), "=r"(r[1]), "=r"(r[2]), "=r"(r[3]) : "r"(addr));
}
__device__ __forceinline__ void mma_bf16(float* d, const uint32_t* a, uint32_t b0, uint32_t b1) {
    asm volatile("mma.sync.aligned.m16n8k16.row.col.f32.bf16.bf16.f32 "
                 "{%0,%1,%2,%3}, {%4,%5,%6,%7}, {%8,%9}, {%0,%1,%2,%3};"
                 : "+f"(d[0]), "+f"(d[1]), "+f"(d[2]), "+f"(d[3])
                 : "r"(a[0]), "r"(a[1]), "r"(a[2]), "r"(a[3]), "r"(b0), "r"(b1));
}
__device__ __forceinline__ uint32_t bits2(__nv_bfloat162 v) {
    return *reinterpret_cast<uint32_t*>(&v);
}

// fast asinh: sign(v) * log(|v| + sqrt(v^2+1)), MUFU-based
__device__ __forceinline__ float fast_asinh(float v) {
    float av = fabsf(v);
    float w  = __logf(av + __fsqrt_rn(fmaf(av, av, 1.0f)));
    return copysignf(w, v);
}
// fast tanh: 1 - 2/(e^{2x}+1)
__device__ __forceinline__ float fast_tanh(float x) {
    float e2 = __expf(2.0f * x);
    return 1.0f - __fdividef(2.0f, e2 + 1.0f);
}

// Split a loaded float4 into truncated-bf16 hi + RN-bf16 lo, store to smem; add v^2 to acc.
__device__ __forceinline__ void split_store(float4 v, __nv_bfloat16* row,
                                            __nv_bfloat16* loRow, int c4, float& acc)
{
    acc = fmaf(v.x, v.x, acc);
    acc = fmaf(v.y, v.y, acc);
    acc = fmaf(v.z, v.z, acc);
    acc = fmaf(v.w, v.w, acc);
    uint32_t bx = __float_as_uint(v.x), by = __float_as_uint(v.y);
    uint32_t bz = __float_as_uint(v.z), bw = __float_as_uint(v.w);
    uint32_t hi01 = __byte_perm(bx, by, 0x7632);
    uint32_t hi23 = __byte_perm(bz, bw, 0x7632);
    float rx = v.x - __uint_as_float(bx & 0xFFFF0000u);
    float ry = v.y - __uint_as_float(by & 0xFFFF0000u);
    float rz = v.z - __uint_as_float(bz & 0xFFFF0000u);
    float rw = v.w - __uint_as_float(bw & 0xFFFF0000u);
    __nv_bfloat162 lo01 = __float22bfloat162_rn(make_float2(rx, ry));
    __nv_bfloat162 lo23 = __float22bfloat162_rn(make_float2(rz, rw));
    *reinterpret_cast<uint2*>(&row[c4 * 4])   = make_uint2(hi01, hi23);
    *reinterpret_cast<uint2*>(&loRow[c4 * 4]) = make_uint2(bits2(lo01), bits2(lo23));
}

// logits[b][k] = 2*an_k * asinh( 2*(S*xa + T*ya)*den / (den^2 - (S^2*x2 + 2*S*T*xy + T^2*y2)) )
// g = z_k . y_b, xy = s_k*g, ya = t_k*g, S = 1+2xy+y2, den = 1+2xy+x2*y2, T = 1-x2

__global__ void __launch_bounds__(NTHREADS, 2)
mlr_logits_kernel(const float* __restrict__ Y,   // output_before (B, D)
                  const float* __restrict__ Z,   // z_mlr (K, D)
                  const float* __restrict__ R,   // mlr_r (K, 1)
                  float* __restrict__ Out)       // (B, K)
{
    extern __shared__ char smem[];
    __nv_bfloat16* AHI = reinterpret_cast<__nv_bfloat16*>(smem);           // BM*PB
    __nv_bfloat16* ALO = AHI + BM * PB;                                     // BM*PB
    __nv_bfloat16* ZHI = ALO + BM * PB;                                     // BN*PB
    __nv_bfloat16* ZLO = ZHI + BN * PB;                                     // BN*PB
    float* s_y2  = reinterpret_cast<float*>(ZLO + BN * PB);                 // BM
    float* s_zn2 = s_y2 + BM;                                               // BN

    const int tid  = threadIdx.x;
    const int b0   = blockIdx.x * BM;
    const int k0   = blockIdx.y * BN;
    const int warp = tid >> 5;
    const int lane = tid & 31;

    // GEMM/epilogue indices (computed early; kl needed for R prefetch)
    const int mw = (warp >> 2) * 16;      // 0,16
    const int nw = (warp & 3) * 8;        // 0,8,16,24
    const int g  = lane >> 2;
    const int c  = lane & 3;
    const int kl = nw + 2 * c;

    // prefetch R for this thread's two k-columns (ready long before epilogue)
    const float rv0 = R[k0 + kl];
    const float rv1 = R[k0 + kl + 1];

    // ---- split phase: warp w owns Y rows 4w..4w+3 and Z rows 4w..4w+3 ----
    // Issue ALL 16 LDG.128 first (single latency exposure), then split.
    {
        const int r0 = warp * 4;
        const int cA = lane, cB = lane + 32;
        float4 vy[4][2], vz[4][2];
        #pragma unroll
        for (int rr = 0; rr < 4; rr++) {
            const float4* yp = reinterpret_cast<const float4*>(Y + (size_t)(b0 + r0 + rr) * DD);
            const float4* zp = reinterpret_cast<const float4*>(Z + (size_t)(k0 + r0 + rr) * DD);
            vy[rr][0] = yp[cA];  vy[rr][1] = yp[cB];
            vz[rr][0] = zp[cA];  vz[rr][1] = zp[cB];
        }

        float aY[4] = {0.f, 0.f, 0.f, 0.f};
        float aZ[4] = {0.f, 0.f, 0.f, 0.f};
        #pragma unroll
        for (int rr = 0; rr < 4; rr++) {
            split_store(vy[rr][0], &AHI[(r0 + rr) * PB], &ALO[(r0 + rr) * PB], cA, aY[rr]);
            split_store(vy[rr][1], &AHI[(r0 + rr) * PB], &ALO[(r0 + rr) * PB], cB, aY[rr]);
            split_store(vz[rr][0], &ZHI[(r0 + rr) * PB], &ZLO[(r0 + rr) * PB], cA, aZ[rr]);
            split_store(vz[rr][1], &ZHI[(r0 + rr) * PB], &ZLO[(r0 + rr) * PB], cB, aZ[rr]);
        }

        // 8 concurrent butterfly reductions
        #pragma unroll
        for (int off = 16; off > 0; off >>= 1) {
            #pragma unroll
            for (int rr = 0; rr < 4; rr++) {
                aY[rr] += __shfl_xor_sync(0xffffffffu, aY[rr], off);
                aZ[rr] += __shfl_xor_sync(0xffffffffu, aZ[rr], off);
            }
        }
        if (lane == 0) {
            #pragma unroll
            for (int rr = 0; rr < 4; rr++) {
                s_y2[r0 + rr]  = aY[rr];
                s_zn2[r0 + rr] = aZ[rr];
            }
        }
    }
    __syncthreads();   // the ONLY block-wide barrier

    // ---- tensor GEMM: 8 warps (2m x 4n), warp tile 16m x 8n, m16n8k16 bf16 ----
    const int rowA = mw + (lane & 15);
    const int offA = (lane >> 4) * 16;             // bytes
    const int rowB = nw + (lane & 7);
    const int offB = (lane >> 3) * 16;             // bytes: 0,16,32,48

    uint32_t aAH = cvta_smem(AHI) + rowA * (PB * 2) + offA;
    uint32_t aAL = cvta_smem(ALO) + rowA * (PB * 2) + offA;
    uint32_t aBH = cvta_smem(ZHI) + rowB * (PB * 2) + offB;
    uint32_t aBL = cvta_smem(ZLO) + rowB * (PB * 2) + offB;

    float accP[4] = {0,0,0,0};   // hi*hi
    float accQ[4] = {0,0,0,0};   // hi*lo
    float accS[4] = {0,0,0,0};   // lo*hi

    // double-buffered fragments
    uint32_t aH0[2][4], aH1[2][4], aL0[2][4], aL1[2][4], bH[2][4], bL[2][4];

    ldmat_x4(aH0[0], aAH);
    ldmat_x4(aH1[0], aAH + 32);
    ldmat_x4(aL0[0], aAL);
    ldmat_x4(aL1[0], aAL + 32);
    ldmat_x4(bH[0],  aBH);
    ldmat_x4(bL[0],  aBL);

    #pragma unroll
    for (int t = 0; t < DD / 32; t++) {          // 8 iterations of k32
        const int cur = t & 1, nxt = cur ^ 1;
        if (t < DD / 32 - 1) {
            const uint32_t oA = (t + 1) * 64;    // 32 bf16 = 64 bytes
            ldmat_x4(aH0[nxt], aAH + oA);
            ldmat_x4(aH1[nxt], aAH + oA + 32);
            ldmat_x4(aL0[nxt], aAL + oA);
            ldmat_x4(aL1[nxt], aAL + oA + 32);
            ldmat_x4(bH[nxt],  aBH + oA);
            ldmat_x4(bL[nxt],  aBL + oA);
        }
        mma_bf16(accP, aH0[cur], bH[cur][0], bH[cur][1]);
        mma_bf16(accQ, aH0[cur], bL[cur][0], bL[cur][1]);
        mma_bf16(accS, aL0[cur], bH[cur][0], bH[cur][1]);
        mma_bf16(accP, aH1[cur], bH[cur][2], bH[cur][3]);
        mma_bf16(accQ, aH1[cur], bL[cur][2], bL[cur][3]);
        mma_bf16(accS, aL1[cur], bH[cur][2], bH[cur][3]);
    }

    // ---- epilogue: per-thread inline scalars (redundant x8, fully parallel) ----
    float s0, t0, x20, xa0, a20, s1, t1, x21, xa1, a21;
    {
        float zn2 = s_zn2[kl];
        float zn  = __fsqrt_rn(zn2);
        float un  = fmaxf(fabsf(rv0) * zn, 1e-15f);
        float s   = -fast_tanh(un) * __fdividef(rv0, un);
        float th  = fast_tanh(rv0);
        float ic2 = 1.0f - th * th;
        float an  = zn * ic2;
        float t   = __fdividef(ic2, fmaxf(an, 1e-12f));
        s0 = s; t0 = t; x20 = s * s * zn2; xa0 = s * zn2 * t; a20 = 2.0f * an;
    }
    {
        float zn2 = s_zn2[kl + 1];
        float zn  = __fsqrt_rn(zn2);
        float un  = fmaxf(fabsf(rv1) * zn, 1e-15f);
        float s   = -fast_tanh(un) * __fdividef(rv1, un);
        float th  = fast_tanh(rv1);
        float ic2 = 1.0f - th * th;
        float an  = zn * ic2;
        float t   = __fdividef(ic2, fmaxf(an, 1e-12f));
        s1 = s; t1 = t; x21 = s * s * zn2; xa1 = s * zn2 * t; a21 = 2.0f * an;
    }
    const float T0 = 1.0f - x20, T1 = 1.0f - x21;
    const int brow[2] = { mw + g, mw + g + 8 };

    #pragma unroll
    for (int i = 0; i < 2; i++) {
        const float y2 = s_y2[brow[i]];
        const float g0 = accP[i * 2 + 0] + accQ[i * 2 + 0] + accS[i * 2 + 0];
        const float g1 = accP[i * 2 + 1] + accQ[i * 2 + 1] + accS[i * 2 + 1];

        float xy = s0 * g0;
        float ya = t0 * g0;
        float Sv  = fmaf(2.0f, xy, 1.0f) + y2;
        float den = fmaf(2.0f, xy, 1.0f) + x20 * y2;
        float Pv  = Sv * Sv * x20 + 2.0f * Sv * T0 * xy + T0 * T0 * y2;
        float v0  = 2.0f * (Sv * xa0 + T0 * ya) * __fdividef(den, den * den - Pv);
        float o0  = a20 * fast_asinh(v0);

        xy  = s1 * g1;
        ya  = t1 * g1;
        Sv  = fmaf(2.0f, xy, 1.0f) + y2;
        den = fmaf(2.0f, xy, 1.0f) + x21 * y2;
        Pv  = Sv * Sv * x21 + 2.0f * Sv * T1 * xy + T1 * T1 * y2;
        float v1 = 2.0f * (Sv * xa1 + T1 * ya) * __fdividef(den, den * den - Pv);
        float o1 = a21 * fast_asinh(v1);

        *reinterpret_cast<float2*>(&Out[(size_t)(b0 + brow[i]) * KK + (k0 + kl)]) =
            make_float2(o0, o1);
    }
}

extern "C" void kernel_launch(void* const* d_in, const int* in_sizes, int n_in,
                              void* d_out, int out_size)
{
    const float* Y = (const float*)d_in[0];   // output_before (2048, 256)
    const float* Z = (const float*)d_in[1];   // z_mlr (128, 256)
    const float* R = (const float*)d_in[2];   // mlr_r (128, 1)
    float* Out = (float*)d_out;               // (2048, 128)

    size_t shmem = (size_t)(2 * BM * PB + 2 * BN * PB) * sizeof(__nv_bfloat16)
                 + (size_t)(BM + BN) * sizeof(float);
    cudaFuncSetAttribute(mlr_logits_kernel,
                         cudaFuncAttributeMaxDynamicSharedMemorySize, (int)shmem);

    dim3 grid(BB / BM, KK / BN);   // 64 x 4 = 256 blocks
    mlr_logits_kernel<<<grid, NTHREADS, shmem>>>(Y, Z, R, Out);
}

// round 15
// speedup vs baseline: 1.4640x; 1.0144x over previous
#include <cuda_runtime.h>
#include <cuda_bf16.h>
#include <math.h>
#include <stdint.h>

// Problem constants (fixed by setup_inputs): B=2048, K=128, D=256
#define BB 2048
#define KK 128
#define DD 256

#define BM 32       // b-rows per block
#define BN 32       // k-cols per block
#define PB 264      // smem row pitch in bf16 units (528 B; 16B-aligned, conflict-free ldmatrix)
#define NTHREADS 256

__device__ __forceinline__ uint32_t cvta_smem(const void* p) {
    return (uint32_t)__cvta_generic_to_shared(p);
}
__device__ __forceinline__ void ldmat_x4(uint32_t* r, uint32_t addr) {
    asm volatile("ldmatrix.sync.aligned.m8n8.x4.shared.b16 {%0,%1,%2,%3}, [%4];"
                 : "=r"(r[0]), "=r"(r[1]), "=r"(r[2]), "=r"(r[3]) : "r"(addr));
}
__device__ __forceinline__ void mma_bf16(float* d, const uint32_t* a, uint32_t b0, uint32_t b1) {
    asm volatile("mma.sync.aligned.m16n8k16.row.col.f32.bf16.bf16.f32 "
                 "{%0,%1,%2,%3}, {%4,%5,%6,%7}, {%8,%9}, {%0,%1,%2,%3};"
                 : "+f"(d[0]), "+f"(d[1]), "+f"(d[2]), "+f"(d[3])
                 : "r"(a[0]), "r"(a[1]), "r"(a[2]), "r"(a[3]), "r"(b0), "r"(b1));
}
__device__ __forceinline__ uint32_t bits2(__nv_bfloat162 v) {
    return *reinterpret_cast<uint32_t*>(&v);
}

// fast asinh: sign(v) * log(|v| + sqrt(v^2+1)), MUFU-based
__device__ __forceinline__ float fast_asinh(float v) {
    float av = fabsf(v);
    float w  = __logf(av + __fsqrt_rn(fmaf(av, av, 1.0f)));
    return copysignf(w, v);
}
// fast tanh: 1 - 2/(e^{2x}+1)
__device__ __forceinline__ float fast_tanh(float x) {
    float e2 = __expf(2.0f * x);
    return 1.0f - __fdividef(2.0f, e2 + 1.0f);
}

// Split a loaded float4 into truncated-bf16 hi + RN-bf16 lo, store to smem; add v^2 to acc.
__device__ __forceinline__ void split_store(float4 v, __nv_bfloat16* row,
                                            __nv_bfloat16* loRow, int c4, float& acc)
{
    acc = fmaf(v.x, v.x, acc);
    acc = fmaf(v.y, v.y, acc);
    acc = fmaf(v.z, v.z, acc);
    acc = fmaf(v.w, v.w, acc);
    uint32_t bx = __float_as_uint(v.x), by = __float_as_uint(v.y);
    uint32_t bz = __float_as_uint(v.z), bw = __float_as_uint(v.w);
    uint32_t hi01 = __byte_perm(bx, by, 0x7632);
    uint32_t hi23 = __byte_perm(bz, bw, 0x7632);
    float rx = v.x - __uint_as_float(bx & 0xFFFF0000u);
    float ry = v.y - __uint_as_float(by & 0xFFFF0000u);
    float rz = v.z - __uint_as_float(bz & 0xFFFF0000u);
    float rw = v.w - __uint_as_float(bw & 0xFFFF0000u);
    __nv_bfloat162 lo01 = __float22bfloat162_rn(make_float2(rx, ry));
    __nv_bfloat162 lo23 = __float22bfloat162_rn(make_float2(rz, rw));
    *reinterpret_cast<uint2*>(&row[c4 * 4])   = make_uint2(hi01, hi23);
    *reinterpret_cast<uint2*>(&loRow[c4 * 4]) = make_uint2(bits2(lo01), bits2(lo23));
}

// logits[b][k] = 2*an_k * asinh( 2*(S*xa + T*ya)*den / (den^2 - (S^2*x2 + 2*S*T*xy + T^2*y2)) )
// g = z_k . y_b, xy = s_k*g, ya = t_k*g, S = 1+2xy+y2, den = 1+2xy+x2*y2, T = 1-x2

__global__ void __launch_bounds__(NTHREADS, 2)
mlr_logits_kernel(const float* __restrict__ Y,   // output_before (B, D)
                  const float* __restrict__ Z,   // z_mlr (K, D)
                  const float* __restrict__ R,   // mlr_r (K, 1)
                  float* __restrict__ Out)       // (B, K)
{
    extern __shared__ char smem[];
    __nv_bfloat16* AHI = reinterpret_cast<__nv_bfloat16*>(smem);           // BM*PB
    __nv_bfloat16* ALO = AHI + BM * PB;                                     // BM*PB
    __nv_bfloat16* ZHI = ALO + BM * PB;                                     // BN*PB
    __nv_bfloat16* ZLO = ZHI + BN * PB;                                     // BN*PB
    float* s_y2  = reinterpret_cast<float*>(ZLO + BN * PB);                 // BM
    float* s_s   = s_y2 + BM;                                               // BN
    float* s_t   = s_s + BN;
    float* s_x2  = s_t + BN;
    float* s_xa  = s_x2 + BN;
    float* s_an2 = s_xa + BN;

    const int tid  = threadIdx.x;
    const int b0   = blockIdx.x * BM;
    const int k0   = blockIdx.y * BN;
    const int warp = tid >> 5;
    const int lane = tid & 31;

    // per-warp early R load: lanes 0-3 fetch R for Z rows 4w..4w+3
    float rv = 0.f;
    if (lane < 4) rv = R[k0 + warp * 4 + lane];

    // ---- split phase: warp w owns Y rows 4w..4w+3 and Z rows 4w..4w+3 ----
    {
        const int r0 = warp * 4;
        const int cA = lane, cB = lane + 32;
        float4 vy[4][2], vz[4][2];
        #pragma unroll
        for (int rr = 0; rr < 4; rr++) {
            const float4* yp = reinterpret_cast<const float4*>(Y + (size_t)(b0 + r0 + rr) * DD);
            const float4* zp = reinterpret_cast<const float4*>(Z + (size_t)(k0 + r0 + rr) * DD);
            vy[rr][0] = yp[cA];  vy[rr][1] = yp[cB];
            vz[rr][0] = zp[cA];  vz[rr][1] = zp[cB];
        }

        float aY[4] = {0.f, 0.f, 0.f, 0.f};
        float aZ[4] = {0.f, 0.f, 0.f, 0.f};
        #pragma unroll
        for (int rr = 0; rr < 4; rr++) {
            split_store(vy[rr][0], &AHI[(r0 + rr) * PB], &ALO[(r0 + rr) * PB], cA, aY[rr]);
            split_store(vy[rr][1], &AHI[(r0 + rr) * PB], &ALO[(r0 + rr) * PB], cB, aY[rr]);
            split_store(vz[rr][0], &ZHI[(r0 + rr) * PB], &ZLO[(r0 + rr) * PB], cA, aZ[rr]);
            split_store(vz[rr][1], &ZHI[(r0 + rr) * PB], &ZLO[(r0 + rr) * PB], cB, aZ[rr]);
        }

        // 8 concurrent butterfly reductions (all lanes end with full sums)
        #pragma unroll
        for (int off = 16; off > 0; off >>= 1) {
            #pragma unroll
            for (int rr = 0; rr < 4; rr++) {
                aY[rr] += __shfl_xor_sync(0xffffffffu, aY[rr], off);
                aZ[rr] += __shfl_xor_sync(0xffffffffu, aZ[rr], off);
            }
        }
        if (lane == 0) {
            #pragma unroll
            for (int rr = 0; rr < 4; rr++) s_y2[r0 + rr] = aY[rr];
        }

        // lanes 0-3: compute per-k scalars for Z rows r0+lane (MUFU latency
        // overlaps remaining split work + barrier wait)
        float zn2 = aZ[0];
        if (lane == 1) zn2 = aZ[1];
        if (lane == 2) zn2 = aZ[2];
        if (lane == 3) zn2 = aZ[3];
        if (lane < 4) {
            const int row = r0 + lane;
            float zn  = __fsqrt_rn(zn2);
            float un  = fmaxf(fabsf(rv) * zn, 1e-15f);
            float s   = -fast_tanh(un) * __fdividef(rv, un);
            float th  = fast_tanh(rv);
            float ic2 = 1.0f - th * th;      // 1/cosh(r)^2
            float an  = zn * ic2;
            float t   = __fdividef(ic2, fmaxf(an, 1e-12f));
            s_s[row]   = s;
            s_t[row]   = t;
            s_x2[row]  = s * s * zn2;
            s_xa[row]  = s * zn2 * t;
            s_an2[row] = 2.0f * an;
        }
    }
    __syncthreads();   // the ONLY block-wide barrier

    // ---- tensor GEMM: 8 warps (2m x 4n), warp tile 16m x 8n, m16n8k16 bf16 ----
    const int mw = (warp >> 2) * 16;      // 0,16
    const int nw = (warp & 3) * 8;        // 0,8,16,24
    const int g  = lane >> 2;
    const int c  = lane & 3;
    const int kl = nw + 2 * c;

    const int rowA = mw + (lane & 15);
    const int offA = (lane >> 4) * 16;             // bytes
    const int rowB = nw + (lane & 7);
    const int offB = (lane >> 3) * 16;             // bytes: 0,16,32,48

    uint32_t aAH = cvta_smem(AHI) + rowA * (PB * 2) + offA;
    uint32_t aAL = cvta_smem(ALO) + rowA * (PB * 2) + offA;
    uint32_t aBH = cvta_smem(ZHI) + rowB * (PB * 2) + offB;
    uint32_t aBL = cvta_smem(ZLO) + rowB * (PB * 2) + offB;

    float accP[4] = {0,0,0,0};   // hi*hi
    float accQ[4] = {0,0,0,0};   // hi*lo
    float accS[4] = {0,0,0,0};   // lo*hi

    // double-buffered fragments
    uint32_t aH0[2][4], aH1[2][4], aL0[2][4], aL1[2][4], bH[2][4], bL[2][4];

    ldmat_x4(aH0[0], aAH);
    ldmat_x4(aH1[0], aAH + 32);
    ldmat_x4(aL0[0], aAL);
    ldmat_x4(aL1[0], aAL + 32);
    ldmat_x4(bH[0],  aBH);
    ldmat_x4(bL[0],  aBL);

    #pragma unroll
    for (int t = 0; t < DD / 32; t++) {          // 8 iterations of k32
        const int cur = t & 1, nxt = cur ^ 1;
        if (t < DD / 32 - 1) {
            const uint32_t oA = (t + 1) * 64;    // 32 bf16 = 64 bytes
            ldmat_x4(aH0[nxt], aAH + oA);
            ldmat_x4(aH1[nxt], aAH + oA + 32);
            ldmat_x4(aL0[nxt], aAL + oA);
            ldmat_x4(aL1[nxt], aAL + oA + 32);
            ldmat_x4(bH[nxt],  aBH + oA);
            ldmat_x4(bL[nxt],  aBL + oA);
        }
        mma_bf16(accP, aH0[cur], bH[cur][0], bH[cur][1]);
        mma_bf16(accQ, aH0[cur], bL[cur][0], bL[cur][1]);
        mma_bf16(accS, aL0[cur], bH[cur][0], bH[cur][1]);
        mma_bf16(accP, aH1[cur], bH[cur][2], bH[cur][3]);
        mma_bf16(accQ, aH1[cur], bL[cur][2], bL[cur][3]);
        mma_bf16(accS, aL1[cur], bH[cur][2], bH[cur][3]);
    }

    // ---- epilogue: scalars from smem, 4 outputs per thread ----
    const float s0  = s_s[kl],   s1  = s_s[kl + 1];
    const float t0  = s_t[kl],   t1  = s_t[kl + 1];
    const float x20 = s_x2[kl],  x21 = s_x2[kl + 1];
    const float xa0 = s_xa[kl],  xa1 = s_xa[kl + 1];
    const float a20 = s_an2[kl], a21 = s_an2[kl + 1];
    const float T0 = 1.0f - x20, T1 = 1.0f - x21;
    const int brow[2] = { mw + g, mw + g + 8 };

    #pragma unroll
    for (int i = 0; i < 2; i++) {
        const float y2 = s_y2[brow[i]];
        const float g0 = accP[i * 2 + 0] + accQ[i * 2 + 0] + accS[i * 2 + 0];
        const float g1 = accP[i * 2 + 1] + accQ[i * 2 + 1] + accS[i * 2 + 1];

        float xy = s0 * g0;
        float ya = t0 * g0;
        float Sv  = fmaf(2.0f, xy, 1.0f) + y2;
        float den = fmaf(2.0f, xy, 1.0f) + x20 * y2;
        float Pv  = Sv * Sv * x20 + 2.0f * Sv * T0 * xy + T0 * T0 * y2;
        float v0  = 2.0f * (Sv * xa0 + T0 * ya) * __fdividef(den, den * den - Pv);
        float o0  = a20 * fast_asinh(v0);

        xy  = s1 * g1;
        ya  = t1 * g1;
        Sv  = fmaf(2.0f, xy, 1.0f) + y2;
        den = fmaf(2.0f, xy, 1.0f) + x21 * y2;
        Pv  = Sv * Sv * x21 + 2.0f * Sv * T1 * xy + T1 * T1 * y2;
        float v1 = 2.0f * (Sv * xa1 + T1 * ya) * __fdividef(den, den * den - Pv);
        float o1 = a21 * fast_asinh(v1);

        *reinterpret_cast<float2*>(&Out[(size_t)(b0 + brow[i]) * KK + (k0 + kl)]) =
            make_float2(o0, o1);
    }
}

extern "C" void kernel_launch(void* const* d_in, const int* in_sizes, int n_in,
                              void* d_out, int out_size)
{
    const float* Y = (const float*)d_in[0];   // output_before (2048, 256)
    const float* Z = (const float*)d_in[1];   // z_mlr (128, 256)
    const float* R = (const float*)d_in[2];   // mlr_r (128, 1)
    float* Out = (float*)d_out;               // (2048, 128)

    size_t shmem = (size_t)(2 * BM * PB + 2 * BN * PB) * sizeof(__nv_bfloat16)
                 + (size_t)(BM + 5 * BN) * sizeof(float);
    cudaFuncSetAttribute(mlr_logits_kernel,
                         cudaFuncAttributeMaxDynamicSharedMemorySize, (int)shmem);

    dim3 grid(BB / BM, KK / BN);   // 64 x 4 = 256 blocks
    mlr_logits_kernel<<<grid, NTHREADS, shmem>>>(Y, Z, R, Out);
}